// round 1
// baseline (speedup 1.0000x reference)
#include <cuda_runtime.h>
#include <cuda_bf16.h>
#include <cstdint>

#define N_NODES  200000
#define N_EDGES  200000
#define N_GRAPHS 128
#define IN_F     256
#define HID_F    128
#define OUT_F    128

// ---------------- scratch (static device globals; no allocation) -------------
__device__ float g_H1[(size_t)N_NODES * HID_F];   // x @ W1
__device__ float g_A1[(size_t)N_NODES * HID_F];   // conv1 output (x2)
__device__ float g_H2[(size_t)N_NODES * HID_F];   // relu(A1)@W2a + R[batch]
__device__ float g_O [(size_t)N_NODES * HID_F];   // conv2 pre-relu
__device__ float g_deg [N_NODES];
__device__ float g_dinv[N_NODES];
__device__ float g_R   [N_GRAPHS * HID_F];        // relu(x[root]) @ W2[128:384]
__device__ float g_gsum[N_GRAPHS * HID_F];
__device__ float g_gcnt[N_GRAPHS];

// ---------------- small kernels ----------------------------------------------
__global__ void k_init(void) {
    int i = blockIdx.x * blockDim.x + threadIdx.x;
    if (i < N_NODES) g_deg[i] = 1.0f;           // self-loop
    if (i < N_GRAPHS * HID_F) g_gsum[i] = 0.0f;
    if (i < N_GRAPHS) g_gcnt[i] = 0.0f;
}

__global__ void k_degree(const int* __restrict__ ei) {
    int e = blockIdx.x * blockDim.x + threadIdx.x;
    if (e >= N_EDGES) return;
    int d = ei[N_EDGES + e];
    atomicAdd(&g_deg[d], 1.0f);
}

__global__ void k_dinv(void) {
    int i = blockIdx.x * blockDim.x + threadIdx.x;
    if (i >= N_NODES) return;
    g_dinv[i] = rsqrtf(g_deg[i]);
}

// dst[i] = src_feat[i] * dinv[i]^2 + bias  (self-loop term + bias, full write)
__global__ void k_self(const float* __restrict__ H, float* __restrict__ D,
                       const float* __restrict__ bias) {
    int idx = blockIdx.x * blockDim.x + threadIdx.x;   // float4 index
    if (idx >= N_NODES * (HID_F / 4)) return;
    int node = idx >> 5;          // /32
    int c4   = (idx & 31) << 2;   // *4
    float s = g_dinv[node]; s = s * s;
    float4 h = *(const float4*)(H + (size_t)node * HID_F + c4);
    float4 b = *(const float4*)(bias + c4);
    float4 r;
    r.x = h.x * s + b.x; r.y = h.y * s + b.y;
    r.z = h.z * s + b.z; r.w = h.w * s + b.w;
    *(float4*)(D + (size_t)node * HID_F + c4) = r;
}

// one warp per edge: D[dst] += H[src] * dinv[src]*dinv[dst]
__global__ void k_edge(const float* __restrict__ H, float* __restrict__ D,
                       const int* __restrict__ ei) {
    int e = blockIdx.x * (blockDim.x >> 5) + (threadIdx.x >> 5);
    if (e >= N_EDGES) return;
    int lane = threadIdx.x & 31;
    int s = ei[e], d = ei[N_EDGES + e];
    float c = g_dinv[s] * g_dinv[d];
    float4 v = *(const float4*)(H + (size_t)s * HID_F + lane * 4);
    float* o = D + (size_t)d * HID_F + lane * 4;
    atomicAdd(o + 0, v.x * c);
    atomicAdd(o + 1, v.y * c);
    atomicAdd(o + 2, v.z * c);
    atomicAdd(o + 3, v.w * c);
}

// R[g] = relu(x[root[g]]) @ W2[128:384]   (128 blocks x 128 threads)
__global__ void k_rootgemm(const float* __restrict__ x,
                           const int* __restrict__ root,
                           const float* __restrict__ W2) {
    __shared__ float xr[IN_F];
    int g = blockIdx.x, t = threadIdx.x;
    int r = root[g];
    xr[t]       = fmaxf(x[(size_t)r * IN_F + t], 0.0f);
    xr[t + 128] = fmaxf(x[(size_t)r * IN_F + t + 128], 0.0f);
    __syncthreads();
    float acc = 0.0f;
#pragma unroll 8
    for (int k = 0; k < IN_F; k++)
        acc += xr[k] * W2[(size_t)(HID_F + k) * OUT_F + t];
    g_R[g * HID_F + t] = acc;
}

// ---------------- tiled SGEMM: C[M,128] = op(A[M,K]) @ B[K,128] (+ R[batch]) --
#define BM 128
#define BN 128
#define BKk 8
#define TM 8
#define TN 8

template<bool RELU_A, bool ADD_R>
__global__ __launch_bounds__(256)
void k_gemm(const float* __restrict__ A, const float* __restrict__ B,
            float* __restrict__ C, const int* __restrict__ batch,
            int M, int K) {
    __shared__ float As[BKk][BM];
    __shared__ float Bs[BKk][BN];
    const int tid = threadIdx.x;
    const int block_row = blockIdx.x * BM;
    const int a_row = tid >> 1;            // 0..127
    const int a_col = (tid & 1) << 2;      // 0 or 4
    const int b_row = tid >> 5;            // 0..7
    const int b_col = (tid & 31) << 2;     // 0..124
    const int tx = tid & 15, ty = tid >> 4;

    float acc[TM][TN];
#pragma unroll
    for (int i = 0; i < TM; i++)
#pragma unroll
        for (int j = 0; j < TN; j++) acc[i][j] = 0.0f;

    for (int k0 = 0; k0 < K; k0 += BKk) {
        int gr = block_row + a_row;
        float4 av = make_float4(0.f, 0.f, 0.f, 0.f);
        if (gr < M) av = *(const float4*)(A + (size_t)gr * K + k0 + a_col);
        if (RELU_A) {
            av.x = fmaxf(av.x, 0.f); av.y = fmaxf(av.y, 0.f);
            av.z = fmaxf(av.z, 0.f); av.w = fmaxf(av.w, 0.f);
        }
        As[a_col + 0][a_row] = av.x;
        As[a_col + 1][a_row] = av.y;
        As[a_col + 2][a_row] = av.z;
        As[a_col + 3][a_row] = av.w;
        float4 bv = *(const float4*)(B + (size_t)(k0 + b_row) * BN + b_col);
        *(float4*)&Bs[b_row][b_col] = bv;
        __syncthreads();

#pragma unroll
        for (int k = 0; k < BKk; k++) {
            float ar[TM], br[TN];
#pragma unroll
            for (int i = 0; i < TM; i++) ar[i] = As[k][ty * TM + i];
#pragma unroll
            for (int j = 0; j < TN; j++) br[j] = Bs[k][tx * TN + j];
#pragma unroll
            for (int i = 0; i < TM; i++)
#pragma unroll
                for (int j = 0; j < TN; j++)
                    acc[i][j] += ar[i] * br[j];
        }
        __syncthreads();
    }

#pragma unroll
    for (int i = 0; i < TM; i++) {
        int row = block_row + ty * TM + i;
        if (row >= M) continue;
        float* crow = C + (size_t)row * BN + tx * TN;
        if (ADD_R) {
            const float* rr = g_R + (size_t)batch[row] * HID_F + tx * TN;
            float4 r0 = *(const float4*)(rr);
            float4 r1 = *(const float4*)(rr + 4);
            float4 o0 = make_float4(acc[i][0] + r0.x, acc[i][1] + r0.y,
                                    acc[i][2] + r0.z, acc[i][3] + r0.w);
            float4 o1 = make_float4(acc[i][4] + r1.x, acc[i][5] + r1.y,
                                    acc[i][6] + r1.z, acc[i][7] + r1.w);
            *(float4*)(crow)     = o0;
            *(float4*)(crow + 4) = o1;
        } else {
            float4 o0 = make_float4(acc[i][0], acc[i][1], acc[i][2], acc[i][3]);
            float4 o1 = make_float4(acc[i][4], acc[i][5], acc[i][6], acc[i][7]);
            *(float4*)(crow)     = o0;
            *(float4*)(crow + 4) = o1;
        }
    }
}

// ---------------- graph mean reduction (batch is sorted) ----------------------
#define NPB 512
__global__ void k_reduce(const int* __restrict__ batch) {
    int c = threadIdx.x;                      // 0..127 (column)
    int start = blockIdx.x * NPB;
    if (start >= N_NODES) return;
    int end = min(start + NPB, N_NODES);
    int curg = batch[start];
    float acc = 0.0f; int cnt = 0;
    for (int i = start; i < end; i++) {
        int g = batch[i];
        if (g != curg) {
            atomicAdd(&g_gsum[curg * HID_F + c], acc);
            if (c == 0) atomicAdd(&g_gcnt[curg], (float)cnt);
            acc = 0.0f; cnt = 0; curg = g;
        }
        acc += fmaxf(g_O[(size_t)i * HID_F + c], 0.0f);
        cnt++;
    }
    atomicAdd(&g_gsum[curg * HID_F + c], acc);
    if (c == 0) atomicAdd(&g_gcnt[curg], (float)cnt);
}

// out[g, 0:128]   = gsum/max(cnt,1)
// out[g, 128:256] = cnt>0 ? A1[root[g]] : 0      (exact mean of constant rows)
__global__ void k_final(const int* __restrict__ root, float* __restrict__ out) {
    int g = blockIdx.x, c = threadIdx.x;      // 256 threads
    float cnt = g_gcnt[g];
    float v;
    if (c < HID_F) {
        v = g_gsum[g * HID_F + c] / fmaxf(cnt, 1.0f);
    } else {
        v = (cnt > 0.0f) ? g_A1[(size_t)root[g] * HID_F + (c - HID_F)] : 0.0f;
    }
    out[g * 256 + c] = v;
}

// ---------------- launch ------------------------------------------------------
extern "C" void kernel_launch(void* const* d_in, const int* in_sizes, int n_in,
                              void* d_out, int out_size) {
    const float* x     = (const float*)d_in[0];
    const int*   ei    = (const int*)  d_in[1];
    const int*   batch = (const int*)  d_in[2];
    const int*   root  = (const int*)  d_in[3];
    const float* W1    = (const float*)d_in[4];
    const float* b1    = (const float*)d_in[5];
    const float* W2    = (const float*)d_in[6];
    const float* b2    = (const float*)d_in[7];
    float* out = (float*)d_out;

    float *H1, *A1, *H2, *O;
    cudaGetSymbolAddress((void**)&H1, g_H1);
    cudaGetSymbolAddress((void**)&A1, g_A1);
    cudaGetSymbolAddress((void**)&H2, g_H2);
    cudaGetSymbolAddress((void**)&O,  g_O);

    const int gemm_blocks = (N_NODES + BM - 1) / BM;           // 1563
    const int self_blocks = (N_NODES * (HID_F / 4) + 255) / 256;
    const int edge_blocks = (N_EDGES + 7) / 8;                  // 8 edges/block @256thr

    // degree + norm
    k_init  <<<(N_NODES + 255) / 256, 256>>>();
    k_degree<<<(N_EDGES + 255) / 256, 256>>>(ei);
    k_dinv  <<<(N_NODES + 255) / 256, 256>>>();

    // conv1
    k_gemm<false, false><<<gemm_blocks, 256>>>(x, W1, H1, nullptr, N_NODES, IN_F);
    k_self<<<self_blocks, 256>>>(H1, A1, b1);
    k_edge<<<edge_blocks, 256>>>(H1, A1, ei);

    // root-feature GEMM (factored second half of W2)
    k_rootgemm<<<N_GRAPHS, 128>>>(x, root, W2);

    // conv2 (A = relu(A1), B = W2[0:128], + R[batch] in epilogue)
    k_gemm<true, true><<<gemm_blocks, 256>>>(A1, W2, H2, batch, N_NODES, HID_F);
    k_self<<<self_blocks, 256>>>(H2, O, b2);
    k_edge<<<edge_blocks, 256>>>(H2, O, ei);

    // graph mean + output
    k_reduce<<<(N_NODES + NPB - 1) / NPB, HID_F>>>(batch);
    k_final <<<N_GRAPHS, 256>>>(root, out);
}

// round 3
// speedup vs baseline: 2.1789x; 2.1789x over previous
#include <cuda_runtime.h>
#include <cuda_bf16.h>
#include <cstdint>

#define N_NODES  200000
#define N_EDGES  200000
#define N_GRAPHS 128
#define IN_F     256
#define HID_F    128
#define OUT_F    128

// ---------------- scratch (static device globals; no allocation) -------------
__device__ float g_H1[(size_t)N_NODES * HID_F];   // x @ W1
__device__ float g_A1[(size_t)N_NODES * HID_F];   // conv1 output (x2)
__device__ float g_H2[(size_t)N_NODES * HID_F];   // relu(A1)@W2a + R[batch]
__device__ float g_O [(size_t)N_NODES * HID_F];   // conv2 pre-relu
__device__ float g_deg [N_NODES];
__device__ float g_dinv[N_NODES];
__device__ float g_R   [N_GRAPHS * HID_F];        // relu(x[root]) @ W2[128:384]
__device__ float g_gsum[N_GRAPHS * HID_F];
__device__ float g_gcnt[N_GRAPHS];
// transposed bf16 hi/lo weights: Wt[n*K + k]
__device__ __nv_bfloat16 g_Wt1h[HID_F * IN_F];
__device__ __nv_bfloat16 g_Wt1l[HID_F * IN_F];
__device__ __nv_bfloat16 g_Wt2h[HID_F * HID_F];
__device__ __nv_bfloat16 g_Wt2l[HID_F * HID_F];

// ---------------- helpers -----------------------------------------------------
__device__ __forceinline__ void mma_bf16(float* c, const uint32_t* a, const uint32_t* b) {
    asm volatile(
        "mma.sync.aligned.m16n8k16.row.col.f32.bf16.bf16.f32 "
        "{%0,%1,%2,%3}, {%4,%5,%6,%7}, {%8,%9}, {%0,%1,%2,%3};"
        : "+f"(c[0]), "+f"(c[1]), "+f"(c[2]), "+f"(c[3])
        : "r"(a[0]), "r"(a[1]), "r"(a[2]), "r"(a[3]), "r"(b[0]), "r"(b[1]));
}

__device__ __forceinline__ void split2(float a, float b, uint32_t& h, uint32_t& l) {
    __nv_bfloat162 hh = __floats2bfloat162_rn(a, b);
    float ra = a - __bfloat162float(hh.x);
    float rb = b - __bfloat162float(hh.y);
    __nv_bfloat162 ll = __floats2bfloat162_rn(ra, rb);
    h = *reinterpret_cast<uint32_t*>(&hh);
    l = *reinterpret_cast<uint32_t*>(&ll);
}

// ---------------- small kernels ----------------------------------------------
__global__ void k_init(void) {
    int i = blockIdx.x * blockDim.x + threadIdx.x;
    if (i < N_NODES) g_deg[i] = 1.0f;           // self-loop
    if (i < N_GRAPHS * HID_F) g_gsum[i] = 0.0f;
    if (i < N_GRAPHS) g_gcnt[i] = 0.0f;
}

__global__ void k_degree(const int* __restrict__ ei) {
    int e = blockIdx.x * blockDim.x + threadIdx.x;
    if (e >= N_EDGES) return;
    atomicAdd(&g_deg[ei[N_EDGES + e]], 1.0f);
}

__global__ void k_dinv(void) {
    int i = blockIdx.x * blockDim.x + threadIdx.x;
    if (i >= N_NODES) return;
    g_dinv[i] = rsqrtf(g_deg[i]);
}

// transpose + bf16 hi/lo split of weights: Wt[n*K+k] = split(W[k*HID+n])
__global__ void k_prepW(const float* __restrict__ W1, const float* __restrict__ W2) {
    int n = blockIdx.x;      // 0..127
    int k = threadIdx.x;     // 0..255
    float v = W1[(size_t)k * HID_F + n];
    __nv_bfloat16 h = __float2bfloat16(v);
    g_Wt1h[n * IN_F + k] = h;
    g_Wt1l[n * IN_F + k] = __float2bfloat16(v - __bfloat162float(h));
    if (k < HID_F) {
        float v2 = W2[(size_t)k * OUT_F + n];
        __nv_bfloat16 h2 = __float2bfloat16(v2);
        g_Wt2h[n * HID_F + k] = h2;
        g_Wt2l[n * HID_F + k] = __float2bfloat16(v2 - __bfloat162float(h2));
    }
}

// one warp per edge: D[dst] += H[src] * dinv[src]*dinv[dst]
__global__ void k_edge(const float* __restrict__ H, float* __restrict__ D,
                       const int* __restrict__ ei) {
    int e = blockIdx.x * (blockDim.x >> 5) + (threadIdx.x >> 5);
    if (e >= N_EDGES) return;
    int lane = threadIdx.x & 31;
    int s = ei[e], d = ei[N_EDGES + e];
    float c = g_dinv[s] * g_dinv[d];
    float4 v = *(const float4*)(H + (size_t)s * HID_F + lane * 4);
    float* o = D + (size_t)d * HID_F + lane * 4;
    atomicAdd(o + 0, v.x * c);
    atomicAdd(o + 1, v.y * c);
    atomicAdd(o + 2, v.z * c);
    atomicAdd(o + 3, v.w * c);
}

// R[g] = relu(x[root[g]]) @ W2[128:384]
__global__ void k_rootgemm(const float* __restrict__ x,
                           const int* __restrict__ root,
                           const float* __restrict__ W2) {
    __shared__ float xr[IN_F];
    int g = blockIdx.x, t = threadIdx.x;
    int r = root[g];
    xr[t]       = fmaxf(x[(size_t)r * IN_F + t], 0.0f);
    xr[t + 128] = fmaxf(x[(size_t)r * IN_F + t + 128], 0.0f);
    __syncthreads();
    float acc = 0.0f;
#pragma unroll 8
    for (int k = 0; k < IN_F; k++)
        acc += xr[k] * W2[(size_t)(HID_F + k) * OUT_F + t];
    g_R[g * HID_F + t] = acc;
}

// ---------------- tensor-core GEMM: C[M,128] = op(A[M,K]) @ Wt^T --------------
// mma.sync m16n8k16 bf16, 3-term split (hi*hi + hi*lo + lo*hi), fp32 accum.
// Fused epilogue: H = C (+ R[batch]);  D = H * dinv^2 + bias.
#define BK   32
#define SAPD 40      // smem stride in halves (pad 8)

template<int K, bool RELU_A, bool ADD_R>
__global__ __launch_bounds__(256, 2)
void k_tgemm(const float* __restrict__ A,
             const __nv_bfloat16* __restrict__ Bh,
             const __nv_bfloat16* __restrict__ Bl,
             float* __restrict__ H, float* __restrict__ D,
             const float* __restrict__ bias,
             const int* __restrict__ batch, int M) {
    __shared__ uint16_t sA[2][128 * SAPD];  // [hi|lo][row*SAPD + k]
    __shared__ uint16_t sB[2][128 * SAPD];  // [hi|lo][n*SAPD + k]

    const int tid  = threadIdx.x;
    const int wid  = tid >> 5;
    const int lane = tid & 31;
    const int g8   = lane >> 2;            // 0..7
    const int t2   = (lane & 3) * 2;       // 0,2,4,6
    const int warp_m = (wid >> 2) * 64;    // 0 or 64
    const int warp_n = (wid & 3) * 32;     // 0..96
    const int blockRow = blockIdx.x * 128;

    float acc[4][4][4];
#pragma unroll
    for (int i = 0; i < 4; i++)
#pragma unroll
        for (int j = 0; j < 4; j++)
#pragma unroll
            for (int q = 0; q < 4; q++) acc[i][j][q] = 0.0f;

    for (int k0 = 0; k0 < K; k0 += BK) {
        __syncthreads();
        // ---- A tile: 128 x 32 fp32 -> split bf16 hi/lo ----
#pragma unroll
        for (int it = 0; it < 4; it++) {
            int linear = tid + it * 256;          // 0..1023 float4 slots
            int row = linear >> 3;
            int c4  = (linear & 7) * 4;
            int gr = blockRow + row;
            float4 v = make_float4(0.f, 0.f, 0.f, 0.f);
            if (gr < M) v = *(const float4*)(A + (size_t)gr * K + k0 + c4);
            if (RELU_A) {
                v.x = fmaxf(v.x, 0.f); v.y = fmaxf(v.y, 0.f);
                v.z = fmaxf(v.z, 0.f); v.w = fmaxf(v.w, 0.f);
            }
            uint32_t h01, l01, h23, l23;
            split2(v.x, v.y, h01, l01);
            split2(v.z, v.w, h23, l23);
            int ho = row * SAPD + c4;
            *(uint32_t*)&sA[0][ho]     = h01;
            *(uint32_t*)&sA[0][ho + 2] = h23;
            *(uint32_t*)&sA[1][ho]     = l01;
            *(uint32_t*)&sA[1][ho + 2] = l23;
        }
        // ---- B tiles: 128 n x 32 k bf16 (pretransposed, presplit) ----
#pragma unroll
        for (int it = 0; it < 2; it++) {
            int linear = tid + it * 256;          // 0..511 uint4 slots
            int n  = linear >> 2;
            int k8 = (linear & 3) * 8;
            size_t gi = ((size_t)n * K + k0 + k8) / 8;   // uint4 index
            int ho = n * SAPD + k8;
            *(uint4*)&sB[0][ho] = ((const uint4*)Bh)[gi];
            *(uint4*)&sB[1][ho] = ((const uint4*)Bl)[gi];
        }
        __syncthreads();

        // ---- compute: 2 k16-steps x 3 split terms x (4m x 4n) mma ----
#pragma unroll
        for (int ks = 0; ks < 2; ks++) {
            const int kk = ks * 16;
            uint32_t ah[4][4], al[4][4], bh[4][2], bl[4][2];
#pragma unroll
            for (int mt = 0; mt < 4; mt++) {
                int r = warp_m + mt * 16 + g8;
                int ho = r * SAPD + kk + t2;
                ah[mt][0] = *(const uint32_t*)&sA[0][ho];
                ah[mt][1] = *(const uint32_t*)&sA[0][ho + 8 * SAPD];
                ah[mt][2] = *(const uint32_t*)&sA[0][ho + 8];
                ah[mt][3] = *(const uint32_t*)&sA[0][ho + 8 * SAPD + 8];
                al[mt][0] = *(const uint32_t*)&sA[1][ho];
                al[mt][1] = *(const uint32_t*)&sA[1][ho + 8 * SAPD];
                al[mt][2] = *(const uint32_t*)&sA[1][ho + 8];
                al[mt][3] = *(const uint32_t*)&sA[1][ho + 8 * SAPD + 8];
            }
#pragma unroll
            for (int nt = 0; nt < 4; nt++) {
                int n = warp_n + nt * 8 + g8;
                int ho = n * SAPD + kk + t2;
                bh[nt][0] = *(const uint32_t*)&sB[0][ho];
                bh[nt][1] = *(const uint32_t*)&sB[0][ho + 8];
                bl[nt][0] = *(const uint32_t*)&sB[1][ho];
                bl[nt][1] = *(const uint32_t*)&sB[1][ho + 8];
            }
#pragma unroll
            for (int mt = 0; mt < 4; mt++)
#pragma unroll
                for (int nt = 0; nt < 4; nt++) {
                    mma_bf16(acc[mt][nt], ah[mt], bh[nt]);
                    mma_bf16(acc[mt][nt], ah[mt], bl[nt]);
                    mma_bf16(acc[mt][nt], al[mt], bh[nt]);
                }
        }
    }

    // ---- epilogue: H = acc (+R[batch]);  D = H*dinv^2 + bias ----
#pragma unroll
    for (int mt = 0; mt < 4; mt++) {
#pragma unroll
        for (int half = 0; half < 2; half++) {
            int row = blockRow + warp_m + mt * 16 + g8 + half * 8;
            if (row >= M) continue;
            float dv = g_dinv[row];
            float ds = dv * dv;
            const float* Rrow = ADD_R ? (g_R + (size_t)batch[row] * HID_F) : nullptr;
#pragma unroll
            for (int nt = 0; nt < 4; nt++) {
                int col = warp_n + nt * 8 + t2;
                float v0 = acc[mt][nt][half * 2 + 0];
                float v1 = acc[mt][nt][half * 2 + 1];
                if (ADD_R) { v0 += Rrow[col]; v1 += Rrow[col + 1]; }
                *(float2*)(H + (size_t)row * HID_F + col) = make_float2(v0, v1);
                float b0 = bias[col], b1 = bias[col + 1];
                *(float2*)(D + (size_t)row * HID_F + col) =
                    make_float2(v0 * ds + b0, v1 * ds + b1);
            }
        }
    }
}

// ---------------- graph mean reduction (batch is sorted) ----------------------
#define NPB 512
__global__ void k_reduce(const int* __restrict__ batch) {
    int c = threadIdx.x;                      // 0..127 (column)
    int start = blockIdx.x * NPB;
    if (start >= N_NODES) return;
    int end = min(start + NPB, N_NODES);
    int curg = batch[start];
    float acc = 0.0f; int cnt = 0;
    for (int i = start; i < end; i++) {
        int g = batch[i];
        if (g != curg) {
            atomicAdd(&g_gsum[curg * HID_F + c], acc);
            if (c == 0) atomicAdd(&g_gcnt[curg], (float)cnt);
            acc = 0.0f; cnt = 0; curg = g;
        }
        acc += fmaxf(g_O[(size_t)i * HID_F + c], 0.0f);
        cnt++;
    }
    atomicAdd(&g_gsum[curg * HID_F + c], acc);
    if (c == 0) atomicAdd(&g_gcnt[curg], (float)cnt);
}

__global__ void k_final(const int* __restrict__ root, float* __restrict__ out) {
    int g = blockIdx.x, c = threadIdx.x;      // 256 threads
    float cnt = g_gcnt[g];
    float v;
    if (c < HID_F) {
        v = g_gsum[g * HID_F + c] / fmaxf(cnt, 1.0f);
    } else {
        v = (cnt > 0.0f) ? g_A1[(size_t)root[g] * HID_F + (c - HID_F)] : 0.0f;
    }
    out[g * 256 + c] = v;
}

// ---------------- launch ------------------------------------------------------
extern "C" void kernel_launch(void* const* d_in, const int* in_sizes, int n_in,
                              void* d_out, int out_size) {
    const float* x     = (const float*)d_in[0];
    const int*   ei    = (const int*)  d_in[1];
    const int*   batch = (const int*)  d_in[2];
    const int*   root  = (const int*)  d_in[3];
    const float* W1    = (const float*)d_in[4];
    const float* b1    = (const float*)d_in[5];
    const float* W2    = (const float*)d_in[6];
    const float* b2    = (const float*)d_in[7];
    float* out = (float*)d_out;

    float *H1, *A1, *H2, *O;
    __nv_bfloat16 *Wt1h, *Wt1l, *Wt2h, *Wt2l;
    cudaGetSymbolAddress((void**)&H1, g_H1);
    cudaGetSymbolAddress((void**)&A1, g_A1);
    cudaGetSymbolAddress((void**)&H2, g_H2);
    cudaGetSymbolAddress((void**)&O,  g_O);
    cudaGetSymbolAddress((void**)&Wt1h, g_Wt1h);
    cudaGetSymbolAddress((void**)&Wt1l, g_Wt1l);
    cudaGetSymbolAddress((void**)&Wt2h, g_Wt2h);
    cudaGetSymbolAddress((void**)&Wt2l, g_Wt2l);

    const int gemm_blocks = (N_NODES + 127) / 128;             // 1563
    const int edge_blocks = (N_EDGES + 7) / 8;                 // 8 edges/block @256thr

    // degree + norm + weight prep
    k_init  <<<(N_NODES + 255) / 256, 256>>>();
    k_degree<<<(N_EDGES + 255) / 256, 256>>>(ei);
    k_dinv  <<<(N_NODES + 255) / 256, 256>>>();
    k_prepW <<<HID_F, IN_F>>>(W1, W2);

    // conv1: H1 = x@W1 (tensor); A1 = H1*dinv^2 + b1 (fused); edges accumulate
    k_tgemm<IN_F, false, false><<<gemm_blocks, 256>>>(
        x, Wt1h, Wt1l, H1, A1, b1, batch, N_NODES);
    k_edge<<<edge_blocks, 256>>>(H1, A1, ei);

    // root-feature GEMM (factored second half of W2)
    k_rootgemm<<<N_GRAPHS, 128>>>(x, root, W2);

    // conv2: H2 = relu(A1)@W2a + R[batch]; O = H2*dinv^2 + b2; edges accumulate
    k_tgemm<HID_F, true, true><<<gemm_blocks, 256>>>(
        A1, Wt2h, Wt2l, H2, O, b2, batch, N_NODES);
    k_edge<<<edge_blocks, 256>>>(H2, O, ei);

    // graph mean + output
    k_reduce<<<(N_NODES + NPB - 1) / NPB, HID_F>>>(batch);
    k_final <<<N_GRAPHS, 256>>>(root, out);
}

// round 6
// speedup vs baseline: 2.7846x; 1.2780x over previous
#include <cuda_runtime.h>
#include <cuda_bf16.h>
#include <cstdint>

#define N_NODES  200000
#define N_EDGES  200000
#define N_GRAPHS 128
#define IN_F     256
#define HID_F    128
#define OUT_F    128

// ---------------- scratch (static device globals; no allocation) -------------
__device__ float g_H1[(size_t)N_NODES * HID_F];   // x @ W1
__device__ float g_A1[(size_t)N_NODES * HID_F];   // conv1 output (x2)
__device__ float g_H2[(size_t)N_NODES * HID_F];   // relu(A1)@W2a + R[batch]
__device__ float g_O [(size_t)N_NODES * HID_F];   // conv2 pre-relu
__device__ float g_deg [N_NODES];
__device__ float g_dinv[N_NODES];
__device__ float g_R   [N_GRAPHS * HID_F];        // relu(x[root]) @ W2[128:384]
__device__ float g_gsum[N_GRAPHS * HID_F];
__device__ float g_gcnt[N_GRAPHS];
// transposed bf16 hi/lo weights: Wt[n*K + k]
__device__ __nv_bfloat16 g_Wt1h[HID_F * IN_F];
__device__ __nv_bfloat16 g_Wt1l[HID_F * IN_F];
__device__ __nv_bfloat16 g_Wt2h[HID_F * HID_F];
__device__ __nv_bfloat16 g_Wt2l[HID_F * HID_F];

// ---------------- helpers -----------------------------------------------------
__device__ __forceinline__ void mma_bf16(float* c, const uint32_t* a, const uint32_t* b) {
    asm volatile(
        "mma.sync.aligned.m16n8k16.row.col.f32.bf16.bf16.f32 "
        "{%0,%1,%2,%3}, {%4,%5,%6,%7}, {%8,%9}, {%0,%1,%2,%3};"
        : "+f"(c[0]), "+f"(c[1]), "+f"(c[2]), "+f"(c[3])
        : "r"(a[0]), "r"(a[1]), "r"(a[2]), "r"(a[3]), "r"(b[0]), "r"(b[1]));
}

__device__ __forceinline__ void split2(float a, float b, uint32_t& h, uint32_t& l) {
    __nv_bfloat162 hh = __floats2bfloat162_rn(a, b);
    float ra = a - __bfloat162float(hh.x);
    float rb = b - __bfloat162float(hh.y);
    __nv_bfloat162 ll = __floats2bfloat162_rn(ra, rb);
    h = *reinterpret_cast<uint32_t*>(&hh);
    l = *reinterpret_cast<uint32_t*>(&ll);
}

__device__ __forceinline__ void red_v4(float* addr, float a, float b, float c, float d) {
    asm volatile("red.global.add.v4.f32 [%0], {%1, %2, %3, %4};"
        :: "l"(addr), "f"(a), "f"(b), "f"(c), "f"(d) : "memory");
}

__device__ __forceinline__ uint32_t smem_u32(const void* p) {
    uint32_t a;
    asm("{ .reg .u64 t; cvta.to.shared.u64 t, %1; cvt.u32.u64 %0, t; }"
        : "=r"(a) : "l"(p));
    return a;
}
__device__ __forceinline__ void cp_async16(uint32_t saddr, const void* gaddr) {
    asm volatile("cp.async.cg.shared.global [%0], [%1], 16;"
        :: "r"(saddr), "l"(gaddr) : "memory");
}
#define CP_COMMIT() asm volatile("cp.async.commit_group;" ::: "memory")
#define CP_WAIT0()  asm volatile("cp.async.wait_group 0;" ::: "memory")

// ---------------- small kernels ----------------------------------------------
__global__ void k_init(void) {
    int i = blockIdx.x * blockDim.x + threadIdx.x;
    if (i < N_NODES) g_deg[i] = 1.0f;           // self-loop
    if (i < N_GRAPHS * HID_F) g_gsum[i] = 0.0f;
    if (i < N_GRAPHS) g_gcnt[i] = 0.0f;
}

__global__ void k_degree(const int* __restrict__ ei) {
    int e = blockIdx.x * blockDim.x + threadIdx.x;
    if (e >= N_EDGES) return;
    atomicAdd(&g_deg[ei[N_EDGES + e]], 1.0f);
}

__global__ void k_dinv(void) {
    int i = blockIdx.x * blockDim.x + threadIdx.x;
    if (i >= N_NODES) return;
    g_dinv[i] = rsqrtf(g_deg[i]);
}

// transpose + bf16 hi/lo split of weights: Wt[n*K+k] = split(W[k*HID+n])
__global__ void k_prepW(const float* __restrict__ W1, const float* __restrict__ W2) {
    int n = blockIdx.x;      // 0..127
    int k = threadIdx.x;     // 0..255
    float v = W1[(size_t)k * HID_F + n];
    __nv_bfloat16 h = __float2bfloat16(v);
    g_Wt1h[n * IN_F + k] = h;
    g_Wt1l[n * IN_F + k] = __float2bfloat16(v - __bfloat162float(h));
    if (k < HID_F) {
        float v2 = W2[(size_t)k * OUT_F + n];
        __nv_bfloat16 h2 = __float2bfloat16(v2);
        g_Wt2h[n * HID_F + k] = h2;
        g_Wt2l[n * HID_F + k] = __float2bfloat16(v2 - __bfloat162float(h2));
    }
}

// one warp per edge: D[dst] += H[src] * dinv[src]*dinv[dst]   (v4 reductions)
__global__ void k_edge(const float* __restrict__ H, float* __restrict__ D,
                       const int* __restrict__ ei) {
    int e = blockIdx.x * (blockDim.x >> 5) + (threadIdx.x >> 5);
    if (e >= N_EDGES) return;
    int lane = threadIdx.x & 31;
    int s = ei[e], d = ei[N_EDGES + e];
    float c = g_dinv[s] * g_dinv[d];
    float4 v = *(const float4*)(H + (size_t)s * HID_F + lane * 4);
    float* o = D + (size_t)d * HID_F + lane * 4;
    red_v4(o, v.x * c, v.y * c, v.z * c, v.w * c);
}

// R[g] = relu(x[root[g]]) @ W2[128:384]
__global__ void k_rootgemm(const float* __restrict__ x,
                           const int* __restrict__ root,
                           const float* __restrict__ W2) {
    __shared__ float xr[IN_F];
    int g = blockIdx.x, t = threadIdx.x;
    int r = root[g];
    xr[t]       = fmaxf(x[(size_t)r * IN_F + t], 0.0f);
    xr[t + 128] = fmaxf(x[(size_t)r * IN_F + t + 128], 0.0f);
    __syncthreads();
    float acc = 0.0f;
#pragma unroll 8
    for (int k = 0; k < IN_F; k++)
        acc += xr[k] * W2[(size_t)(HID_F + k) * OUT_F + t];
    g_R[g * HID_F + t] = acc;
}

// ---------------- tensor-core GEMM: C[M,128] = op(A[M,K]) @ Wt^T --------------
// mma.sync m16n8k16 bf16, 3-term split, fp32 accum.
// 2-stage pipeline: A via register prefetch + in-core split; B via cp.async.
// Fused epilogue: H = C (+ R[batch]);  D = H * dinv^2 + bias.
#define BK      32
#define SAPD    40                     // smem row stride in halves (pad 8)
#define TILE_H  (128 * SAPD)           // halves per (tile, term)
#define STAGE_H (4 * TILE_H)           // AH, AL, BH, BL
#define TG_SMEM (2 * STAGE_H * 2)      // 81920 bytes

template<int K, bool RELU_A, bool ADD_R>
__global__ __launch_bounds__(256)
void k_tgemm(const float* __restrict__ A,
             const __nv_bfloat16* __restrict__ Bh,
             const __nv_bfloat16* __restrict__ Bl,
             float* __restrict__ H, float* __restrict__ D,
             const float* __restrict__ bias,
             const int* __restrict__ batch, int M) {
    extern __shared__ uint16_t smem[];   // [stage][AH|AL|BH|BL][128*SAPD]
    const uint32_t smem_b = smem_u32(smem);

    const int tid  = threadIdx.x;
    const int wid  = tid >> 5;
    const int lane = tid & 31;
    const int g8   = lane >> 2;            // 0..7
    const int t2   = (lane & 3) * 2;       // 0,2,4,6
    const int warp_m = (wid >> 2) * 64;    // 0 or 64
    const int warp_n = (wid & 3) * 32;     // 0..96
    const int blockRow = blockIdx.x * 128;
    constexpr int NC = K / BK;

    // loader coords: 2 threads per row, 16 k-values each
    const int a_row = tid >> 1;
    const int a_k0  = (tid & 1) * 16;      // float offset within chunk
    const int b_n   = tid >> 1;
    const int b_k   = (tid & 1) * 16;      // half offset within chunk
    const int a_valid = (blockRow + a_row) < M;

    float acc[4][4][4];
#pragma unroll
    for (int i = 0; i < 4; i++)
#pragma unroll
        for (int j = 0; j < 4; j++)
#pragma unroll
            for (int q = 0; q < 4; q++) acc[i][j][q] = 0.0f;

    float4 pa[4];   // 16 floats of A (chunk being prefetched)

    // ---- prologue: A(0) into regs, B(0) via cp.async into stage 0 ----
    {
        const float* ap = A + (size_t)(blockRow + a_row) * K + a_k0;
#pragma unroll
        for (int u = 0; u < 4; u++)
            pa[u] = a_valid ? *(const float4*)(ap + u * 4)
                            : make_float4(0.f, 0.f, 0.f, 0.f);
        const __nv_bfloat16* gh = Bh + (size_t)b_n * K + b_k;
        const __nv_bfloat16* gl = Bl + (size_t)b_n * K + b_k;
        uint32_t sh = smem_b + (uint32_t)(2 * TILE_H + b_n * SAPD + b_k) * 2;
        uint32_t sl = smem_b + (uint32_t)(3 * TILE_H + b_n * SAPD + b_k) * 2;
        cp_async16(sh, gh); cp_async16(sh + 16, gh + 8);
        cp_async16(sl, gl); cp_async16(sl + 16, gl + 8);
        CP_COMMIT();
    }

    for (int c = 0; c < NC; c++) {
        uint16_t* st = smem + (c & 1) * STAGE_H;
        // ---- convert + store A chunk c from regs into stage c&1 ----
        {
            float4 v[4];
#pragma unroll
            for (int u = 0; u < 4; u++) {
                v[u] = pa[u];
                if (RELU_A) {
                    v[u].x = fmaxf(v[u].x, 0.f); v[u].y = fmaxf(v[u].y, 0.f);
                    v[u].z = fmaxf(v[u].z, 0.f); v[u].w = fmaxf(v[u].w, 0.f);
                }
            }
            uint16_t* ah = st;
            uint16_t* al = st + TILE_H;
            int ho = a_row * SAPD + a_k0;
#pragma unroll
            for (int u = 0; u < 4; u++) {
                uint32_t h01, l01, h23, l23;
                split2(v[u].x, v[u].y, h01, l01);
                split2(v[u].z, v[u].w, h23, l23);
                *(uint32_t*)&ah[ho + u * 4]     = h01;
                *(uint32_t*)&ah[ho + u * 4 + 2] = h23;
                *(uint32_t*)&al[ho + u * 4]     = l01;
                *(uint32_t*)&al[ho + u * 4 + 2] = l23;
            }
        }
        CP_WAIT0();            // B chunk c landed
        __syncthreads();
        // ---- kick off chunk c+1 (A regs + B cp.async into other stage) ----
        if (c + 1 < NC) {
            int kc = (c + 1) * BK;
            const float* ap = A + (size_t)(blockRow + a_row) * K + kc + a_k0;
#pragma unroll
            for (int u = 0; u < 4; u++)
                pa[u] = a_valid ? *(const float4*)(ap + u * 4)
                                : make_float4(0.f, 0.f, 0.f, 0.f);
            uint32_t nb = smem_b + (uint32_t)(((c + 1) & 1) * STAGE_H) * 2;
            const __nv_bfloat16* gh = Bh + (size_t)b_n * K + kc + b_k;
            const __nv_bfloat16* gl = Bl + (size_t)b_n * K + kc + b_k;
            uint32_t sh = nb + (uint32_t)(2 * TILE_H + b_n * SAPD + b_k) * 2;
            uint32_t sl = nb + (uint32_t)(3 * TILE_H + b_n * SAPD + b_k) * 2;
            cp_async16(sh, gh); cp_async16(sh + 16, gh + 8);
            cp_async16(sl, gl); cp_async16(sl + 16, gl + 8);
            CP_COMMIT();
        }
        // ---- compute chunk c from stage c&1 ----
        const uint16_t* sAh = st;
        const uint16_t* sAl = st + TILE_H;
        const uint16_t* sBh = st + 2 * TILE_H;
        const uint16_t* sBl = st + 3 * TILE_H;
#pragma unroll
        for (int ks = 0; ks < 2; ks++) {
            const int kk = ks * 16;
            uint32_t ah[4][4], al[4][4], bh[4][2], bl[4][2];
#pragma unroll
            for (int mt = 0; mt < 4; mt++) {
                int r = warp_m + mt * 16 + g8;
                int ho = r * SAPD + kk + t2;
                ah[mt][0] = *(const uint32_t*)&sAh[ho];
                ah[mt][1] = *(const uint32_t*)&sAh[ho + 8 * SAPD];
                ah[mt][2] = *(const uint32_t*)&sAh[ho + 8];
                ah[mt][3] = *(const uint32_t*)&sAh[ho + 8 * SAPD + 8];
                al[mt][0] = *(const uint32_t*)&sAl[ho];
                al[mt][1] = *(const uint32_t*)&sAl[ho + 8 * SAPD];
                al[mt][2] = *(const uint32_t*)&sAl[ho + 8];
                al[mt][3] = *(const uint32_t*)&sAl[ho + 8 * SAPD + 8];
            }
#pragma unroll
            for (int nt = 0; nt < 4; nt++) {
                int n = warp_n + nt * 8 + g8;
                int ho = n * SAPD + kk + t2;
                bh[nt][0] = *(const uint32_t*)&sBh[ho];
                bh[nt][1] = *(const uint32_t*)&sBh[ho + 8];
                bl[nt][0] = *(const uint32_t*)&sBl[ho];
                bl[nt][1] = *(const uint32_t*)&sBl[ho + 8];
            }
#pragma unroll
            for (int mt = 0; mt < 4; mt++)
#pragma unroll
                for (int nt = 0; nt < 4; nt++) {
                    mma_bf16(acc[mt][nt], ah[mt], bh[nt]);
                    mma_bf16(acc[mt][nt], ah[mt], bl[nt]);
                    mma_bf16(acc[mt][nt], al[mt], bh[nt]);
                }
        }
        // single sync per iter: next iter's top-sync covers the WAR on the
        // other stage (every thread has finished reading it one iter earlier).
    }

    // ---- epilogue: H = acc (+R[batch]);  D = H*dinv^2 + bias ----
#pragma unroll
    for (int mt = 0; mt < 4; mt++) {
#pragma unroll
        for (int half = 0; half < 2; half++) {
            int row = blockRow + warp_m + mt * 16 + g8 + half * 8;
            if (row >= M) continue;
            float dv = g_dinv[row];
            float ds = dv * dv;
            const float* Rrow = ADD_R ? (g_R + (size_t)batch[row] * HID_F) : nullptr;
#pragma unroll
            for (int nt = 0; nt < 4; nt++) {
                int col = warp_n + nt * 8 + t2;
                float v0 = acc[mt][nt][half * 2 + 0];
                float v1 = acc[mt][nt][half * 2 + 1];
                if (ADD_R) { v0 += Rrow[col]; v1 += Rrow[col + 1]; }
                *(float2*)(H + (size_t)row * HID_F + col) = make_float2(v0, v1);
                float b0 = bias[col], b1 = bias[col + 1];
                *(float2*)(D + (size_t)row * HID_F + col) =
                    make_float2(v0 * ds + b0, v1 * ds + b1);
            }
        }
    }
}

// ---------------- graph mean reduction (batch is sorted) ----------------------
#define NPB 128
__global__ void k_reduce(const int* __restrict__ batch) {
    int c = threadIdx.x;                      // 0..127 (column)
    int start = blockIdx.x * NPB;
    if (start >= N_NODES) return;
    int end = min(start + NPB, N_NODES);
    int curg = batch[start];
    float acc = 0.0f; int cnt = 0;
    for (int i = start; i < end; i++) {
        int g = batch[i];
        if (g != curg) {
            atomicAdd(&g_gsum[curg * HID_F + c], acc);
            if (c == 0) atomicAdd(&g_gcnt[curg], (float)cnt);
            acc = 0.0f; cnt = 0; curg = g;
        }
        acc += fmaxf(g_O[(size_t)i * HID_F + c], 0.0f);
        cnt++;
    }
    atomicAdd(&g_gsum[curg * HID_F + c], acc);
    if (c == 0) atomicAdd(&g_gcnt[curg], (float)cnt);
}

__global__ void k_final(const int* __restrict__ root, float* __restrict__ out) {
    int g = blockIdx.x, c = threadIdx.x;      // 256 threads
    float cnt = g_gcnt[g];
    float v;
    if (c < HID_F) {
        v = g_gsum[g * HID_F + c] / fmaxf(cnt, 1.0f);
    } else {
        v = (cnt > 0.0f) ? g_A1[(size_t)root[g] * HID_F + (c - HID_F)] : 0.0f;
    }
    out[g * 256 + c] = v;
}

// ---------------- launch ------------------------------------------------------
extern "C" void kernel_launch(void* const* d_in, const int* in_sizes, int n_in,
                              void* d_out, int out_size) {
    const float* x     = (const float*)d_in[0];
    const int*   ei    = (const int*)  d_in[1];
    const int*   batch = (const int*)  d_in[2];
    const int*   root  = (const int*)  d_in[3];
    const float* W1    = (const float*)d_in[4];
    const float* b1    = (const float*)d_in[5];
    const float* W2    = (const float*)d_in[6];
    const float* b2    = (const float*)d_in[7];
    float* out = (float*)d_out;

    float *H1, *A1, *H2, *O;
    __nv_bfloat16 *Wt1h, *Wt1l, *Wt2h, *Wt2l;
    cudaGetSymbolAddress((void**)&H1, g_H1);
    cudaGetSymbolAddress((void**)&A1, g_A1);
    cudaGetSymbolAddress((void**)&H2, g_H2);
    cudaGetSymbolAddress((void**)&O,  g_O);
    cudaGetSymbolAddress((void**)&Wt1h, g_Wt1h);
    cudaGetSymbolAddress((void**)&Wt1l, g_Wt1l);
    cudaGetSymbolAddress((void**)&Wt2h, g_Wt2h);
    cudaGetSymbolAddress((void**)&Wt2l, g_Wt2l);

    cudaFuncSetAttribute(k_tgemm<IN_F, false, false>,
                         cudaFuncAttributeMaxDynamicSharedMemorySize, TG_SMEM);
    cudaFuncSetAttribute(k_tgemm<HID_F, true, true>,
                         cudaFuncAttributeMaxDynamicSharedMemorySize, TG_SMEM);

    const int gemm_blocks = (N_NODES + 127) / 128;             // 1563
    const int edge_blocks = (N_EDGES + 7) / 8;                 // 8 edges/block @256thr

    // degree + norm + weight prep
    k_init  <<<(N_NODES + 255) / 256, 256>>>();
    k_degree<<<(N_EDGES + 255) / 256, 256>>>(ei);
    k_dinv  <<<(N_NODES + 255) / 256, 256>>>();
    k_prepW <<<HID_F, IN_F>>>(W1, W2);

    // conv1: H1 = x@W1 (tensor); A1 = H1*dinv^2 + b1 (fused); edges accumulate
    k_tgemm<IN_F, false, false><<<gemm_blocks, 256, TG_SMEM>>>(
        x, Wt1h, Wt1l, H1, A1, b1, batch, N_NODES);
    k_edge<<<edge_blocks, 256>>>(H1, A1, ei);

    // root-feature GEMM (factored second half of W2)
    k_rootgemm<<<N_GRAPHS, 128>>>(x, root, W2);

    // conv2: H2 = relu(A1)@W2a + R[batch]; O = H2*dinv^2 + b2; edges accumulate
    k_tgemm<HID_F, true, true><<<gemm_blocks, 256, TG_SMEM>>>(
        A1, Wt2h, Wt2l, H2, O, b2, batch, N_NODES);
    k_edge<<<edge_blocks, 256>>>(H2, O, ei);

    // graph mean + output
    k_reduce<<<(N_NODES + NPB - 1) / NPB, 128>>>(batch);
    k_final <<<N_GRAPHS, 256>>>(root, out);
}

// round 9
// speedup vs baseline: 2.8390x; 1.0195x over previous
#include <cuda_runtime.h>
#include <cuda_bf16.h>
#include <cstdint>

#define N_NODES  200000
#define N_EDGES  200000
#define N_GRAPHS 128
#define IN_F     256
#define HID_F    128
#define OUT_F    128

// ---------------- scratch (static device globals; no allocation) -------------
__device__ float g_H1[(size_t)N_NODES * HID_F];   // x @ W1
__device__ float g_A1[(size_t)N_NODES * HID_F];   // conv1 output (x2)
__device__ float g_H2[(size_t)N_NODES * HID_F];   // relu(A1)@W2a + R[batch]
__device__ float g_O [(size_t)N_NODES * HID_F];   // conv2 pre-relu
__device__ float g_deg [N_NODES];
__device__ float g_dinv[N_NODES];
__device__ float g_R   [N_GRAPHS * HID_F];        // relu(x[root]) @ W2[128:384]
__device__ float g_gsum[N_GRAPHS * HID_F];
__device__ float g_gcnt[N_GRAPHS];
// transposed bf16 hi/lo weights: Wt[n*K + k]
__device__ __nv_bfloat16 g_Wt1h[HID_F * IN_F];
__device__ __nv_bfloat16 g_Wt1l[HID_F * IN_F];
__device__ __nv_bfloat16 g_Wt2h[HID_F * HID_F];
__device__ __nv_bfloat16 g_Wt2l[HID_F * HID_F];

// ---------------- helpers -----------------------------------------------------
__device__ __forceinline__ void mma_bf16(float* c, const uint32_t* a, const uint32_t* b) {
    asm volatile(
        "mma.sync.aligned.m16n8k16.row.col.f32.bf16.bf16.f32 "
        "{%0,%1,%2,%3}, {%4,%5,%6,%7}, {%8,%9}, {%0,%1,%2,%3};"
        : "+f"(c[0]), "+f"(c[1]), "+f"(c[2]), "+f"(c[3])
        : "r"(a[0]), "r"(a[1]), "r"(a[2]), "r"(a[3]), "r"(b[0]), "r"(b[1]));
}

__device__ __forceinline__ void split2(float a, float b, uint32_t& h, uint32_t& l) {
    __nv_bfloat162 hh = __floats2bfloat162_rn(a, b);
    float ra = a - __bfloat162float(hh.x);
    float rb = b - __bfloat162float(hh.y);
    __nv_bfloat162 ll = __floats2bfloat162_rn(ra, rb);
    h = *reinterpret_cast<uint32_t*>(&hh);
    l = *reinterpret_cast<uint32_t*>(&ll);
}

__device__ __forceinline__ void red_v4(float* addr, float a, float b, float c, float d) {
    asm volatile("red.global.add.v4.f32 [%0], {%1, %2, %3, %4};"
        :: "l"(addr), "f"(a), "f"(b), "f"(c), "f"(d) : "memory");
}

// ---------------- small kernels ----------------------------------------------
__global__ void k_init(void) {
    int i = blockIdx.x * blockDim.x + threadIdx.x;
    if (i < N_NODES) g_deg[i] = 1.0f;           // self-loop
    if (i < N_GRAPHS * HID_F) g_gsum[i] = 0.0f;
    if (i < N_GRAPHS) g_gcnt[i] = 0.0f;
}

__global__ void k_degree(const int* __restrict__ ei) {
    int e = blockIdx.x * blockDim.x + threadIdx.x;
    if (e >= N_EDGES) return;
    atomicAdd(&g_deg[ei[N_EDGES + e]], 1.0f);
}

__global__ void k_dinv(void) {
    int i = blockIdx.x * blockDim.x + threadIdx.x;
    if (i >= N_NODES) return;
    g_dinv[i] = rsqrtf(g_deg[i]);
}

// transpose + bf16 hi/lo split of weights: Wt[n*K+k] = split(W[k*HID+n])
__global__ void k_prepW(const float* __restrict__ W1, const float* __restrict__ W2) {
    int n = blockIdx.x;      // 0..127
    int k = threadIdx.x;     // 0..255
    float v = W1[(size_t)k * HID_F + n];
    __nv_bfloat16 h = __float2bfloat16(v);
    g_Wt1h[n * IN_F + k] = h;
    g_Wt1l[n * IN_F + k] = __float2bfloat16(v - __bfloat162float(h));
    if (k < HID_F) {
        float v2 = W2[(size_t)k * OUT_F + n];
        __nv_bfloat16 h2 = __float2bfloat16(v2);
        g_Wt2h[n * HID_F + k] = h2;
        g_Wt2l[n * HID_F + k] = __float2bfloat16(v2 - __bfloat162float(h2));
    }
}

// one warp per edge: D[dst] += H[src] * dinv[src]*dinv[dst]   (v4 reductions)
__global__ void k_edge(const float* __restrict__ H, float* __restrict__ D,
                       const int* __restrict__ ei) {
    int e = blockIdx.x * (blockDim.x >> 5) + (threadIdx.x >> 5);
    if (e >= N_EDGES) return;
    int lane = threadIdx.x & 31;
    int s = ei[e], d = ei[N_EDGES + e];
    float c = g_dinv[s] * g_dinv[d];
    float4 v = *(const float4*)(H + (size_t)s * HID_F + lane * 4);
    float* o = D + (size_t)d * HID_F + lane * 4;
    red_v4(o, v.x * c, v.y * c, v.z * c, v.w * c);
}

// R[g] = relu(x[root[g]]) @ W2[128:384]
__global__ void k_rootgemm(const float* __restrict__ x,
                           const int* __restrict__ root,
                           const float* __restrict__ W2) {
    __shared__ float xr[IN_F];
    int g = blockIdx.x, t = threadIdx.x;
    int r = root[g];
    xr[t]       = fmaxf(x[(size_t)r * IN_F + t], 0.0f);
    xr[t + 128] = fmaxf(x[(size_t)r * IN_F + t + 128], 0.0f);
    __syncthreads();
    float acc = 0.0f;
#pragma unroll 8
    for (int k = 0; k < IN_F; k++)
        acc += xr[k] * W2[(size_t)(HID_F + k) * OUT_F + t];
    g_R[g * HID_F + t] = acc;
}

// ---------------- tensor-core GEMM: C[M,128] = op(A[M,K]) @ Wt^T --------------
// mma.sync m16n8k16 bf16, 3-term split (hi*hi + hi*lo + lo*hi), fp32 accum.
// 512 threads / CTA (16 warps, 4x4 warp grid, 32x32 per warp) for occupancy:
// ~110 regs * 512 thr fits the 64K regfile -> 16 warps/SM (vs 8 at 256thr/168r).
// Fused epilogue: H = C (+ R[batch]);  D = H * dinv^2 + bias.
#define BK   32
#define SAPD 40      // smem stride in halves (pad 8)

template<int K, bool RELU_A, bool ADD_R>
__global__ __launch_bounds__(512)
void k_tgemm(const float* __restrict__ A,
             const __nv_bfloat16* __restrict__ Bh,
             const __nv_bfloat16* __restrict__ Bl,
             float* __restrict__ H, float* __restrict__ D,
             const float* __restrict__ bias,
             const int* __restrict__ batch, int M) {
    __shared__ uint16_t sA[2][128 * SAPD];  // [hi|lo][row*SAPD + k]
    __shared__ uint16_t sB[2][128 * SAPD];  // [hi|lo][n*SAPD + k]

    const int tid  = threadIdx.x;
    const int wid  = tid >> 5;             // 0..15
    const int lane = tid & 31;
    const int g8   = lane >> 2;            // 0..7
    const int t2   = (lane & 3) * 2;       // 0,2,4,6
    const int warp_m = (wid >> 2) * 32;    // 0,32,64,96
    const int warp_n = (wid & 3) * 32;     // 0,32,64,96
    const int blockRow = blockIdx.x * 128;

    float acc[2][4][4];
#pragma unroll
    for (int i = 0; i < 2; i++)
#pragma unroll
        for (int j = 0; j < 4; j++)
#pragma unroll
            for (int q = 0; q < 4; q++) acc[i][j][q] = 0.0f;

    for (int k0 = 0; k0 < K; k0 += BK) {
        __syncthreads();
        // ---- A tile: 128 x 32 fp32 -> split bf16 hi/lo (1024 float4 slots) --
#pragma unroll
        for (int it = 0; it < 2; it++) {
            int linear = tid + it * 512;
            int row = linear >> 3;
            int c4  = (linear & 7) * 4;
            int gr = blockRow + row;
            float4 v = make_float4(0.f, 0.f, 0.f, 0.f);
            if (gr < M) v = *(const float4*)(A + (size_t)gr * K + k0 + c4);
            if (RELU_A) {
                v.x = fmaxf(v.x, 0.f); v.y = fmaxf(v.y, 0.f);
                v.z = fmaxf(v.z, 0.f); v.w = fmaxf(v.w, 0.f);
            }
            uint32_t h01, l01, h23, l23;
            split2(v.x, v.y, h01, l01);
            split2(v.z, v.w, h23, l23);
            int ho = row * SAPD + c4;
            *(uint32_t*)&sA[0][ho]     = h01;
            *(uint32_t*)&sA[0][ho + 2] = h23;
            *(uint32_t*)&sA[1][ho]     = l01;
            *(uint32_t*)&sA[1][ho + 2] = l23;
        }
        // ---- B tiles: 128 n x 32 k bf16 (512 uint4 slots per term) ---------
        {
            int n  = tid >> 2;
            int q8 = (tid & 3) * 8;                       // halves offset
            size_t gi = ((size_t)n * K + k0 + q8) / 8;    // uint4 index
            int ho = n * SAPD + q8;
            *(uint4*)&sB[0][ho] = ((const uint4*)Bh)[gi];
            *(uint4*)&sB[1][ho] = ((const uint4*)Bl)[gi];
        }
        __syncthreads();

        // ---- compute: 2 k16-steps x 3 split terms x (2m x 4n) mma ----------
#pragma unroll
        for (int ks = 0; ks < 2; ks++) {
            const int kk = ks * 16;
            uint32_t ah[2][4], al[2][4], bh[4][2], bl[4][2];
#pragma unroll
            for (int mt = 0; mt < 2; mt++) {
                int r = warp_m + mt * 16 + g8;
                int ho = r * SAPD + kk + t2;
                ah[mt][0] = *(const uint32_t*)&sA[0][ho];
                ah[mt][1] = *(const uint32_t*)&sA[0][ho + 8 * SAPD];
                ah[mt][2] = *(const uint32_t*)&sA[0][ho + 8];
                ah[mt][3] = *(const uint32_t*)&sA[0][ho + 8 * SAPD + 8];
                al[mt][0] = *(const uint32_t*)&sA[1][ho];
                al[mt][1] = *(const uint32_t*)&sA[1][ho + 8 * SAPD];
                al[mt][2] = *(const uint32_t*)&sA[1][ho + 8];
                al[mt][3] = *(const uint32_t*)&sA[1][ho + 8 * SAPD + 8];
            }
#pragma unroll
            for (int nt = 0; nt < 4; nt++) {
                int n = warp_n + nt * 8 + g8;
                int ho = n * SAPD + kk + t2;
                bh[nt][0] = *(const uint32_t*)&sB[0][ho];
                bh[nt][1] = *(const uint32_t*)&sB[0][ho + 8];
                bl[nt][0] = *(const uint32_t*)&sB[1][ho];
                bl[nt][1] = *(const uint32_t*)&sB[1][ho + 8];
            }
#pragma unroll
            for (int mt = 0; mt < 2; mt++)
#pragma unroll
                for (int nt = 0; nt < 4; nt++) {
                    mma_bf16(acc[mt][nt], ah[mt], bh[nt]);
                    mma_bf16(acc[mt][nt], ah[mt], bl[nt]);
                    mma_bf16(acc[mt][nt], al[mt], bh[nt]);
                }
        }
    }

    // ---- epilogue: H = acc (+R[batch]);  D = H*dinv^2 + bias ----
#pragma unroll
    for (int mt = 0; mt < 2; mt++) {
#pragma unroll
        for (int half = 0; half < 2; half++) {
            int row = blockRow + warp_m + mt * 16 + g8 + half * 8;
            if (row >= M) continue;
            float dv = g_dinv[row];
            float ds = dv * dv;
            const float* Rrow = ADD_R ? (g_R + (size_t)batch[row] * HID_F) : nullptr;
#pragma unroll
            for (int nt = 0; nt < 4; nt++) {
                int col = warp_n + nt * 8 + t2;
                float v0 = acc[mt][nt][half * 2 + 0];
                float v1 = acc[mt][nt][half * 2 + 1];
                if (ADD_R) { v0 += Rrow[col]; v1 += Rrow[col + 1]; }
                *(float2*)(H + (size_t)row * HID_F + col) = make_float2(v0, v1);
                float b0 = bias[col], b1 = bias[col + 1];
                *(float2*)(D + (size_t)row * HID_F + col) =
                    make_float2(v0 * ds + b0, v1 * ds + b1);
            }
        }
    }
}

// ---------------- graph mean reduction (batch is sorted) ----------------------
// 512 threads = 128 cols x 4 row-lanes; each lane scans rows r, r+4, ... with
// its own run-length chain (atomics only at graph boundaries).
#define NPB 512
__global__ void k_reduce(const int* __restrict__ batch) {
    int c = threadIdx.x & 127;                // column
    int r = threadIdx.x >> 7;                 // 0..3 row-lane
    int start = blockIdx.x * NPB + r;
    if (start >= N_NODES) return;
    int end = min(blockIdx.x * NPB + NPB, N_NODES);
    int curg = -1;
    float acc = 0.0f; int cnt = 0;
    for (int i = start; i < end; i += 4) {
        int g = batch[i];
        if (g != curg) {
            if (curg >= 0) {
                atomicAdd(&g_gsum[curg * HID_F + c], acc);
                if (c == 0) atomicAdd(&g_gcnt[curg], (float)cnt);
            }
            acc = 0.0f; cnt = 0; curg = g;
        }
        acc += fmaxf(g_O[(size_t)i * HID_F + c], 0.0f);
        cnt++;
    }
    if (curg >= 0) {
        atomicAdd(&g_gsum[curg * HID_F + c], acc);
        if (c == 0) atomicAdd(&g_gcnt[curg], (float)cnt);
    }
}

__global__ void k_final(const int* __restrict__ root, float* __restrict__ out) {
    int g = blockIdx.x, c = threadIdx.x;      // 256 threads
    float cnt = g_gcnt[g];
    float v;
    if (c < HID_F) {
        v = g_gsum[g * HID_F + c] / fmaxf(cnt, 1.0f);
    } else {
        v = (cnt > 0.0f) ? g_A1[(size_t)root[g] * HID_F + (c - HID_F)] : 0.0f;
    }
    out[g * 256 + c] = v;
}

// ---------------- launch ------------------------------------------------------
extern "C" void kernel_launch(void* const* d_in, const int* in_sizes, int n_in,
                              void* d_out, int out_size) {
    const float* x     = (const float*)d_in[0];
    const int*   ei    = (const int*)  d_in[1];
    const int*   batch = (const int*)  d_in[2];
    const int*   root  = (const int*)  d_in[3];
    const float* W1    = (const float*)d_in[4];
    const float* b1    = (const float*)d_in[5];
    const float* W2    = (const float*)d_in[6];
    const float* b2    = (const float*)d_in[7];
    float* out = (float*)d_out;

    float *H1, *A1, *H2, *O;
    __nv_bfloat16 *Wt1h, *Wt1l, *Wt2h, *Wt2l;
    cudaGetSymbolAddress((void**)&H1, g_H1);
    cudaGetSymbolAddress((void**)&A1, g_A1);
    cudaGetSymbolAddress((void**)&H2, g_H2);
    cudaGetSymbolAddress((void**)&O,  g_O);
    cudaGetSymbolAddress((void**)&Wt1h, g_Wt1h);
    cudaGetSymbolAddress((void**)&Wt1l, g_Wt1l);
    cudaGetSymbolAddress((void**)&Wt2h, g_Wt2h);
    cudaGetSymbolAddress((void**)&Wt2l, g_Wt2l);

    const int gemm_blocks = (N_NODES + 127) / 128;             // 1563
    const int edge_blocks = (N_EDGES + 7) / 8;                 // 8 edges/block @256thr

    // degree + norm + weight prep
    k_init  <<<(N_NODES + 255) / 256, 256>>>();
    k_degree<<<(N_EDGES + 255) / 256, 256>>>(ei);
    k_dinv  <<<(N_NODES + 255) / 256, 256>>>();
    k_prepW <<<HID_F, IN_F>>>(W1, W2);

    // conv1: H1 = x@W1 (tensor); A1 = H1*dinv^2 + b1 (fused); edges accumulate
    k_tgemm<IN_F, false, false><<<gemm_blocks, 512>>>(
        x, Wt1h, Wt1l, H1, A1, b1, batch, N_NODES);
    k_edge<<<edge_blocks, 256>>>(H1, A1, ei);

    // root-feature GEMM (factored second half of W2)
    k_rootgemm<<<N_GRAPHS, 128>>>(x, root, W2);

    // conv2: H2 = relu(A1)@W2a + R[batch]; O = H2*dinv^2 + b2; edges accumulate
    k_tgemm<HID_F, true, true><<<gemm_blocks, 512>>>(
        A1, Wt2h, Wt2l, H2, O, b2, batch, N_NODES);
    k_edge<<<edge_blocks, 256>>>(H2, O, ei);

    // graph mean + output
    k_reduce<<<(N_NODES + NPB - 1) / NPB, 512>>>(batch);
    k_final <<<N_GRAPHS, 256>>>(root, out);
}